// round 13
// baseline (speedup 1.0000x reference)
#include <cuda_runtime.h>
#include <cuda_bf16.h>

// Problem constants
#define BB 2
#define NN 16384
#define CIN 64
#define SS 4096
#define NSAMP 32

// Output layout (floats): new_xyz | new_features | scores
#define OUT_XYZ_OFF   0
#define OUT_FEAT_OFF  (BB * SS * 3)                       // 24576
#define OUT_SCORE_OFF (OUT_FEAT_OFF + BB * 128 * SS)      // 1073152

// ---------------- scratch (no allocations allowed) ----------------
__device__ float g_featsT[BB * NN * CIN];    // (B,N,C) transposed features, 8 MB
__device__ int   g_ballIdx[BB * SS * NSAMP]; // neighbor indices
__device__ int   g_ballCnt[BB * SS];         // in-ball counts (0 => empty)

typedef unsigned long long u64;

// =================================================================
// Kernel 1: FPS (one 512-thread block per batch; 16 warps)
//  - chunk metadata registerized (lane m of warp w owns chunk w+16m;
//    lane 8 owns the warp's hot chunk); prune = register math.
//  - cwin is warp-private (no sync). Cross-warp state (s_wm/s_wwin)
//    double-buffered by iteration parity => ONE barrier per iter.
//  - DIRTY-SKIP scans, REDUX argmax (dist then inv) => exact
//    (dist<<14)|(16383-idx) winner, first-index tie-break.
// =================================================================
#define FPS_T   512
#define FPS_W   16
#define HOTCAP  1024
#define HOT_TGT 768
#define NCELL   2048

// smem: cxy 131072 | inv16 32768 | hot4 16384 | hist 8192 | cwin f4[144]=2304
#define FPS_SMEM_BYTES (131072 + 32768 + 16384 + 8192 + 2304)

__device__ __forceinline__ float r2_rn(float x, float y, float z)
{
    return __fadd_rn(__fadd_rn(__fmul_rn(x, x), __fmul_rn(y, y)), __fmul_rn(z, z));
}
__device__ __forceinline__ float dist_rn(float x, float y, float z,
                                         float nx, float ny, float nz)
{
    const float dx = __fadd_rn(x, nx);
    const float dy = __fadd_rn(y, ny);
    const float dz = __fadd_rn(z, nz);
    return __fadd_rn(__fadd_rn(__fmul_rn(dx, dx), __fmul_rn(dy, dy)), __fmul_rn(dz, dz));
}

__device__ __forceinline__ int fps_cell(float x, float y, float z,
                                        float mnx, float mny, float mnz,
                                        float isx, float isy, float isz)
{
    int qx = __float2int_rd((x - mnx) * isx); qx = max(0, min(15, qx));
    int qy = __float2int_rd((y - mny) * isy); qy = max(0, min(15, qy));
    int qz = __float2int_rd((z - mnz) * isz); qz = max(0, min(7,  qz));
    return  (qx & 1)        | ((qy & 1) << 1)        | ((qz & 1) << 2)
         | (((qx >> 1) & 1) << 3) | (((qy >> 1) & 1) << 4) | (((qz >> 1) & 1) << 5)
         | (((qx >> 2) & 1) << 6) | (((qy >> 2) & 1) << 7) | (((qz >> 2) & 1) << 8)
         | (((qx >> 3) & 1) << 9) | (((qy >> 3) & 1) << 10);
}

__global__ __launch_bounds__(FPS_T) void fps_kernel(
    const float* __restrict__ xyz, float* __restrict__ out_newxyz)
{
    extern __shared__ unsigned char raw[];
    float2*         cxy   = (float2*)raw;                      // [16384]
    unsigned short* inv16 = (unsigned short*)(cxy + NN);       // [16384]
    float4*         hot4  = (float4*)(inv16 + NN);             // [1024]
    unsigned*       hist  = (unsigned*)(hot4 + HOTCAP);        // [2048]
    float4*         cwin  = (float4*)(hist + NCELL);           // [144] warp-private

    __shared__ u64      s_wm[2][FPS_W];
    __shared__ float4   s_wwin[2][FPS_W];
    __shared__ float    s_wred[FPS_W][6];
    __shared__ unsigned s_wsum[FPS_W], s_wbase[FPS_W];
    __shared__ unsigned s_rh[128];
    __shared__ float    s_r2b, s_thresh;
    __shared__ float    s_grid[6];
    __shared__ unsigned s_hotCnt;

    const int b    = blockIdx.x;
    const int tid  = threadIdx.x;
    const int lane = tid & 31, w = tid >> 5;
    const float* xb = xyz + (size_t)b * NN * 3;

    // ---- pass 0: global AABB ----
    {
        float mnx = 1e30f, mny = 1e30f, mnz = 1e30f;
        float mxx = -1e30f, mxy = -1e30f, mxz = -1e30f;
        for (int i = tid; i < NN; i += FPS_T) {
            const float x = xb[3 * i], y = xb[3 * i + 1], z = xb[3 * i + 2];
            mnx = fminf(mnx, x); mny = fminf(mny, y); mnz = fminf(mnz, z);
            mxx = fmaxf(mxx, x); mxy = fmaxf(mxy, y); mxz = fmaxf(mxz, z);
        }
#pragma unroll
        for (int off = 16; off; off >>= 1) {
            mnx = fminf(mnx, __shfl_xor_sync(0xffffffffu, mnx, off));
            mny = fminf(mny, __shfl_xor_sync(0xffffffffu, mny, off));
            mnz = fminf(mnz, __shfl_xor_sync(0xffffffffu, mnz, off));
            mxx = fmaxf(mxx, __shfl_xor_sync(0xffffffffu, mxx, off));
            mxy = fmaxf(mxy, __shfl_xor_sync(0xffffffffu, mxy, off));
            mxz = fmaxf(mxz, __shfl_xor_sync(0xffffffffu, mxz, off));
        }
        if (lane == 0) {
            s_wred[w][0] = mnx; s_wred[w][1] = mny; s_wred[w][2] = mnz;
            s_wred[w][3] = mxx; s_wred[w][4] = mxy; s_wred[w][5] = mxz;
        }
    }
    for (int i = tid; i < NCELL; i += FPS_T) hist[i] = 0;
    if (tid < 128) s_rh[tid] = 0;
    if (tid == 0) s_hotCnt = 0;
    __syncthreads();
    if (tid == 0) {
        float a0 = 1e30f, a1 = 1e30f, a2 = 1e30f, a3 = -1e30f, a4 = -1e30f, a5 = -1e30f;
        for (int i = 0; i < FPS_W; i++) {
            a0 = fminf(a0, s_wred[i][0]); a1 = fminf(a1, s_wred[i][1]); a2 = fminf(a2, s_wred[i][2]);
            a3 = fmaxf(a3, s_wred[i][3]); a4 = fmaxf(a4, s_wred[i][4]); a5 = fmaxf(a5, s_wred[i][5]);
        }
        s_grid[0] = a0; s_grid[1] = a1; s_grid[2] = a2;
        s_grid[3] = 16.f / fmaxf(a3 - a0, 1e-9f);
        s_grid[4] = 16.f / fmaxf(a4 - a1, 1e-9f);
        s_grid[5] = 8.f  / fmaxf(a5 - a2, 1e-9f);
        const float bx = fmaxf(fabsf(a0), fabsf(a3));
        const float by = fmaxf(fabsf(a1), fabsf(a4));
        const float bz = fmaxf(fabsf(a2), fabsf(a5));
        s_r2b = bx * bx + by * by + bz * bz + 1e-6f;
    }
    __syncthreads();

    const float gmnx = s_grid[0], gmny = s_grid[1], gmnz = s_grid[2];
    const float isx = s_grid[3], isy = s_grid[4], isz = s_grid[5];
    const float r2b = s_r2b;

    // ---- pass 1: r2 histogram -> deterministic hot threshold ----
    for (int i = tid; i < NN; i += FPS_T) {
        const float r2 = r2_rn(xb[3 * i], xb[3 * i + 1], xb[3 * i + 2]);
        const int bin = min(127, (int)(r2 * (128.f / r2b)));
        atomicAdd(&s_rh[bin], 1u);
    }
    __syncthreads();
    if (tid == 0) {
        unsigned acc = 0;
        float thr = 3e38f;
        for (int q = 127; q >= 0; q--) {
            if (acc + s_rh[q] > HOT_TGT) break;
            acc += s_rh[q];
            thr = (float)q * (r2b / 128.f);
        }
        s_thresh = thr;
    }
    __syncthreads();
    const float thresh = s_thresh;

    // ---- pass 2: Morton histogram over cold ----
    for (int i = tid; i < NN; i += FPS_T) {
        const float x = xb[3 * i], y = xb[3 * i + 1], z = xb[3 * i + 2];
        if (r2_rn(x, y, z) < thresh) {
            const int c = fps_cell(x, y, z, gmnx, gmny, gmnz, isx, isy, isz);
            atomicAdd(&hist[c], 1u);
        }
    }
    __syncthreads();

    // ---- exclusive scan of hist[2048] ----
    {
        const int t4 = tid * 4;
        unsigned v[4], s = 0;
#pragma unroll
        for (int q = 0; q < 4; q++) { v[q] = hist[t4 + q]; s += v[q]; }
        unsigned inc = s;
#pragma unroll
        for (int off = 1; off < 32; off <<= 1) {
            const unsigned n = __shfl_up_sync(0xffffffffu, inc, off);
            if (lane >= off) inc += n;
        }
        if (lane == 31) s_wsum[w] = inc;
        __syncthreads();
        if (tid < FPS_W) {
            const unsigned ws = s_wsum[tid];
            unsigned winc = ws;
#pragma unroll
            for (int off = 1; off < FPS_W; off <<= 1) {
                const unsigned n = __shfl_up_sync(0x0000ffffu, winc, off);
                if ((int)tid >= off) winc += n;
            }
            s_wbase[tid] = winc - ws;
        }
        __syncthreads();
        unsigned run = s_wbase[w] + (inc - s);
#pragma unroll
        for (int q = 0; q < 4; q++) { hist[t4 + q] = run; run += v[q]; }
    }
    __syncthreads();

    // ---- pass 3: scatter hot / cold (inv = 16383 - i) ----
    for (int i = tid; i < NN; i += FPS_T) {
        const float x = xb[3 * i], y = xb[3 * i + 1], z = xb[3 * i + 2];
        if (r2_rn(x, y, z) >= thresh) {
            const unsigned pos = atomicAdd(&s_hotCnt, 1u);
            hot4[pos] = make_float4(x, y, z, __uint_as_float(16383u - (unsigned)i));
        } else {
            const int c = fps_cell(x, y, z, gmnx, gmny, gmnz, isx, isy, isz);
            const unsigned slot = atomicAdd(&hist[c], 1u);
            cxy[slot]   = make_float2(x, y);
            inv16[slot] = (unsigned short)(16383u - (unsigned)i);
        }
    }
    __syncthreads();

    const int hc    = (int)s_hotCnt;
    const int coldN = NN - hc;
    const int nch   = (coldN + 127) >> 7;

    // pads (duplicates: identical keys/coords, harmless)
    for (int s2 = hc + tid; s2 < HOTCAP; s2 += FPS_T)
        hot4[s2] = (hc > 0) ? hot4[0]
                            : make_float4(xb[0], xb[1], xb[2], __uint_as_float(16383u));
    for (int s2 = coldN + tid; s2 < nch * 128; s2 += FPS_T) {
        cxy[s2]   = cxy[coldN - 1];
        inv16[s2] = inv16[coldN - 1];
    }
    __syncthreads();

    // ---- per-lane chunk metadata (registers) ----
    float bx0 = 1e30f, bx1 = 1e30f, bx2 = 1e30f;
    float bx3 = -1e30f, bx4 = -1e30f, bx5 = -1e30f;
    u64   mykey = 0ull;

    // hot -> registers (2 pts/thread) + hot AABB -> lane 8
    float hx[2], hy[2], hz[2], hd[2];
    unsigned hinv[2];
    {
        float hmn0 = 1e30f, hmn1 = 1e30f, hmn2 = 1e30f;
        float hmx0 = -1e30f, hmx1 = -1e30f, hmx2 = -1e30f;
#pragma unroll
        for (int k = 0; k < 2; k++) {
            const float4 h = hot4[tid + FPS_T * k];
            hx[k] = h.x; hy[k] = h.y; hz[k] = h.z;
            hinv[k] = __float_as_uint(h.w);
            hd[k] = 1e10f;
            hmn0 = fminf(hmn0, h.x); hmn1 = fminf(hmn1, h.y); hmn2 = fminf(hmn2, h.z);
            hmx0 = fmaxf(hmx0, h.x); hmx1 = fmaxf(hmx1, h.y); hmx2 = fmaxf(hmx2, h.z);
        }
#pragma unroll
        for (int off = 16; off; off >>= 1) {
            hmn0 = fminf(hmn0, __shfl_xor_sync(0xffffffffu, hmn0, off));
            hmn1 = fminf(hmn1, __shfl_xor_sync(0xffffffffu, hmn1, off));
            hmn2 = fminf(hmn2, __shfl_xor_sync(0xffffffffu, hmn2, off));
            hmx0 = fmaxf(hmx0, __shfl_xor_sync(0xffffffffu, hmx0, off));
            hmx1 = fmaxf(hmx1, __shfl_xor_sync(0xffffffffu, hmx1, off));
            hmx2 = fmaxf(hmx2, __shfl_xor_sync(0xffffffffu, hmx2, off));
        }
        if (lane == 8) {
            bx0 = hmn0; bx1 = hmn1; bx2 = hmn2;
            bx3 = hmx0; bx4 = hmx1; bx5 = hmx2;
            mykey = ((u64)__float_as_uint(1e10f)) << 14;
        }
    }

    // cold z + dist regs + saved xy, chunk AABB -> lane m
    float cz[32], cd[32];
    float sx[32], sy[32];
#pragma unroll
    for (int k = 0; k < 32; k++) { cz[k] = 0.f; cd[k] = 1e10f; sx[k] = 0.f; sy[k] = 0.f; }

#pragma unroll
    for (int m = 0; m < 8; m++) {
        const int c = w + FPS_W * m;
        if (c < nch) {
            float lmn0 = 1e30f, lmn1 = 1e30f, lmn2 = 1e30f;
            float lmx0 = -1e30f, lmx1 = -1e30f, lmx2 = -1e30f;
#pragma unroll
            for (int k = 0; k < 4; k++) {
                const int slot = c * 128 + lane + 32 * k;
                const float2 xy = cxy[slot];
                const int oi = 16383 - (int)inv16[slot];
                const float z = __ldg(xb + 3 * oi + 2);
                cz[m * 4 + k] = z;
                sx[m * 4 + k] = xy.x;
                sy[m * 4 + k] = xy.y;
                lmn0 = fminf(lmn0, xy.x); lmn1 = fminf(lmn1, xy.y); lmn2 = fminf(lmn2, z);
                lmx0 = fmaxf(lmx0, xy.x); lmx1 = fmaxf(lmx1, xy.y); lmx2 = fmaxf(lmx2, z);
            }
#pragma unroll
            for (int off = 16; off; off >>= 1) {
                lmn0 = fminf(lmn0, __shfl_xor_sync(0xffffffffu, lmn0, off));
                lmn1 = fminf(lmn1, __shfl_xor_sync(0xffffffffu, lmn1, off));
                lmn2 = fminf(lmn2, __shfl_xor_sync(0xffffffffu, lmn2, off));
                lmx0 = fmaxf(lmx0, __shfl_xor_sync(0xffffffffu, lmx0, off));
                lmx1 = fmaxf(lmx1, __shfl_xor_sync(0xffffffffu, lmx1, off));
                lmx2 = fmaxf(lmx2, __shfl_xor_sync(0xffffffffu, lmx2, off));
            }
            if (lane == m) {
                bx0 = lmn0; bx1 = lmn1; bx2 = lmn2;
                bx3 = lmx0; bx4 = lmx1; bx5 = lmx2;
                mykey = ((u64)__float_as_uint(1e10f)) << 14;
            }
        }
    }
    __syncthreads();

    float* outx = out_newxyz + (size_t)b * SS * 3;
    float ccx = __ldg(xb + 0), ccy = __ldg(xb + 1), ccz = __ldg(xb + 2);

    // per-warp cached summary (registers, refreshed on wflag)
    u64    wmreg = 0ull;
    float4 wwinreg = make_float4(0.f, 0.f, 0.f, 0.f);

    // ---- main loop: ONE barrier per iteration (parity buffers) ----
    for (int j = 0; j < SS; j++) {
        const int p = j & 1;
        if (tid == 0) {
            outx[3 * j + 0] = ccx;
            outx[3 * j + 1] = ccy;
            outx[3 * j + 2] = ccz;
        }
        const float nx = -ccx, ny = -ccy, nz = -ccz;

        // --- prune: pure register math, lanes 0..8 ---
        bool act = false;
        if (lane < 9) {
            const float dxm = fmaxf(fmaxf(__fadd_rn(bx0, nx), -__fadd_rn(bx3, nx)), 0.f);
            const float dym = fmaxf(fmaxf(__fadd_rn(bx1, ny), -__fadd_rn(bx4, ny)), 0.f);
            const float dzm = fmaxf(fmaxf(__fadd_rn(bx2, nz), -__fadd_rn(bx5, nz)), 0.f);
            const float dmin2 = __fadd_rn(__fadd_rn(__fmul_rn(dxm, dxm), __fmul_rn(dym, dym)),
                                          __fmul_rn(dzm, dzm));
            const float cm = __uint_as_float((unsigned)(mykey >> 14));
            act = dmin2 < cm;
        }
        const unsigned mask = __ballot_sync(0xffffffffu, act);
        bool wflag = false;

        // --- hot scan (bit 8) ---
        if ((mask >> 8) & 1u) {
            u64 bk = 0ull; float hbx = 0.f, hby = 0.f, hbz = 0.f;
            bool chg = false;
#pragma unroll
            for (int k = 0; k < 2; k++) {
                const float d = dist_rn(hx[k], hy[k], hz[k], nx, ny, nz);
                const float old = hd[k];
                const float nd = fminf(old, d);
                chg |= (nd < old);
                hd[k] = nd;
                const u64 key = ((u64)__float_as_uint(nd) << 14) | (u64)hinv[k];
                if (key > bk) { bk = key; hbx = hx[k]; hby = hy[k]; hbz = hz[k]; }
            }
            if (__ballot_sync(0xffffffffu, chg)) {
                const unsigned d32 = (unsigned)(bk >> 14);
                const unsigned K32 = __reduce_max_sync(0xffffffffu, d32);
                const unsigned myinv = (unsigned)(bk & 0x3FFFull);
                const unsigned I = __reduce_max_sync(0xffffffffu, (d32 == K32) ? myinv : 0u);
                const unsigned own = __ballot_sync(0xffffffffu, (d32 == K32) && (myinv == I));
                if (lane == (int)(__ffs(own) - 1)) cwin[128 + w] = make_float4(hbx, hby, hbz, 0.f);
                if (lane == 8) mykey = ((u64)K32 << 14) | (u64)I;
                wflag = true;
            }
        }

        // --- cold scans: pass 1 dists; pass 2 keys only if dirty ---
#pragma unroll
        for (int m = 0; m < 8; m++) {
            if ((mask >> m) & 1u) {
                const int c = w + FPS_W * m;
                bool chg = false;
#pragma unroll
                for (int k = 0; k < 4; k++) {
                    const float d = dist_rn(sx[m * 4 + k], sy[m * 4 + k], cz[m * 4 + k],
                                            nx, ny, nz);
                    const float old = cd[m * 4 + k];
                    const float nd = fminf(old, d);
                    chg |= (nd < old);
                    cd[m * 4 + k] = nd;
                }
                if (__ballot_sync(0xffffffffu, chg)) {
                    u64 bk = 0ull; float cbx = 0.f, cby = 0.f, cbz = 0.f;
#pragma unroll
                    for (int k = 0; k < 4; k++) {
                        const int slot = c * 128 + lane + 32 * k;
                        const u64 key = ((u64)__float_as_uint(cd[m * 4 + k]) << 14)
                                      | (u64)inv16[slot];
                        if (key > bk) {
                            bk = key;
                            cbx = sx[m * 4 + k]; cby = sy[m * 4 + k]; cbz = cz[m * 4 + k];
                        }
                    }
                    const unsigned d32 = (unsigned)(bk >> 14);
                    const unsigned K32 = __reduce_max_sync(0xffffffffu, d32);
                    const unsigned myinv = (unsigned)(bk & 0x3FFFull);
                    const unsigned I = __reduce_max_sync(0xffffffffu, (d32 == K32) ? myinv : 0u);
                    const unsigned own = __ballot_sync(0xffffffffu, (d32 == K32) && (myinv == I));
                    if (lane == (int)(__ffs(own) - 1)) cwin[c] = make_float4(cbx, cby, cbz, 0.f);
                    if (lane == m) mykey = ((u64)K32 << 14) | (u64)I;
                    wflag = true;
                }
            }
        }

        // --- warp summary refresh (only if any owned chunk changed) ---
        if (wflag) {
            const unsigned d32 = (lane < 9) ? (unsigned)(mykey >> 14) : 0u;
            const unsigned K = __reduce_max_sync(0xffffffffu, d32);
            const unsigned I = __reduce_max_sync(0xffffffffu,
                (d32 == K) ? (unsigned)(mykey & 0x3FFFull) : 0u);
            wmreg = ((u64)K << 14) | (u64)I;
            const unsigned own = __ballot_sync(0xffffffffu,
                (lane < 9) && (mykey == wmreg));
            const int sl = (int)(__ffs(own) - 1);
            const int src = (sl < 8) ? (w + FPS_W * sl) : (128 + w);
            wwinreg = cwin[src];   // warp-private read (broadcast LDS)
        }
        if (lane == 0) {
            s_wm[p][w] = wmreg;
            s_wwin[p][w] = wwinreg;
        }
        __syncthreads();   // the ONLY barrier in the loop

        // --- block argmax over 16 warp keys (every warp, redundant) ---
        {
            const u64 k = (lane < FPS_W) ? s_wm[p][lane] : 0ull;
            const unsigned d32 = (unsigned)(k >> 14);
            const unsigned K = __reduce_max_sync(0xffffffffu, d32);
            const unsigned I = __reduce_max_sync(0xffffffffu,
                (d32 == K) ? (unsigned)(k & 0x3FFFull) : 0u);
            const u64 W = ((u64)K << 14) | (u64)I;
            const unsigned has = __ballot_sync(0xffffffffu, (lane < FPS_W) && (k == W));
            const int wi = (int)(__ffs(has) - 1);
            const float4 wv = s_wwin[p][wi];
            ccx = wv.x; ccy = wv.y; ccz = wv.z;
        }
        // no second barrier: next iteration writes parity buffer p^1
    }
}

// =================================================================
// Kernel 2: transpose features (B,C,N) -> (B,N,C)
// =================================================================
__global__ void transpose_kernel(const float* __restrict__ f)
{
    __shared__ float tile[32][33];
    const int b  = blockIdx.z;
    const int n0 = blockIdx.x * 32;
    const int c0 = blockIdx.y * 32;
    const int tx = threadIdx.x, ty = threadIdx.y;
    tile[ty][tx] = f[((size_t)b * CIN + (c0 + ty)) * NN + n0 + tx];
    __syncthreads();
    g_featsT[((size_t)b * NN + (n0 + ty)) * CIN + c0 + tx] = tile[tx][ty];
}

// =================================================================
// Kernel 3: ball query (one warp per group), first-32-ascending
// =================================================================
__global__ void ballq_kernel(const float* __restrict__ xyz,
                             const float* __restrict__ newxyz)
{
    const int g    = blockIdx.x * 8 + (threadIdx.x >> 5);
    const int lane = threadIdx.x & 31;
    const int b    = g >> 12;
    const float* xb = xyz + (size_t)b * NN * 3;

    const float cx = newxyz[g * 3 + 0];
    const float cy = newxyz[g * 3 + 1];
    const float cz = newxyz[g * 3 + 2];

    int* out = g_ballIdx + g * NSAMP;
    int cnt = 0;

    for (int base = 0; base < NN && cnt < NSAMP; base += 32) {
        const int i = base + lane;
        const float dx = xb[3 * i + 0] - cx;
        const float dy = xb[3 * i + 1] - cy;
        const float dz = xb[3 * i + 2] - cz;
        const float d2 = __fadd_rn(__fadd_rn(__fmul_rn(dx, dx), __fmul_rn(dy, dy)),
                                   __fmul_rn(dz, dz));
        const bool inb = d2 < 0.25f;
        const unsigned m = __ballot_sync(0xffffffffu, inb);
        const int pos = cnt + __popc(m & ((1u << lane) - 1u));
        if (inb && pos < NSAMP) out[pos] = i;
        cnt += __popc(m);
    }
    __syncwarp();
    if (cnt == 0) {
        out[lane] = 0;
    } else if (cnt < NSAMP) {
        const int first = out[0];
        if (lane >= cnt) out[lane] = first;
    }
    if (lane == 0) g_ballCnt[g] = cnt;
}

// =================================================================
// Kernel 4: fused gather + MLP + pool + agg + score, 8 GROUPS/BLOCK,
// 512 threads. Pool/agg buffers alias dead h1 (actB) storage.
// =================================================================
#define MLP_G     8
#define W1_STRV   72
#define W2_STRV   72
#define W3_STRV   136
#define NBG       256
#define NBS       264
#define W1F       (67 * W1_STRV)
#define W2F       (64 * W2_STRV)
#define W3F       (64 * W3_STRV)
#define ACTA_F    (67 * NBS)
#define ACTB_F    (64 * NBS)
#define MLP2_SMEM_FLOATS (W1F + W2F + W3F + ACTA_F + ACTB_F)

__global__ __launch_bounds__(512, 1) void group_mlp_kernel(
    const float* __restrict__ xyz,
    const float* __restrict__ newxyz,
    const float* __restrict__ w1, const float* __restrict__ b1,
    const float* __restrict__ w2, const float* __restrict__ b2,
    const float* __restrict__ w3, const float* __restrict__ b3,
    const float* __restrict__ wa, const float* __restrict__ ba,
    const float* __restrict__ wc, const float* __restrict__ bc,
    float* __restrict__ d_out)
{
    extern __shared__ float sm[];
    float* w1s     = sm;
    float* w2s     = w1s + W1F;
    float* w3s     = w2s + W2F;
    float* actA    = w3s + W3F;
    float* actB    = actA + ACTA_F;
    float* poolbuf = actB;
    float* pooled  = actB + 4096;
    float* aggv    = actB + 5120;

    __shared__ float bss[384];
    __shared__ float c3[32];
    __shared__ int   idxs[NBG];
    __shared__ int   scnt[8];

    const int blk = blockIdx.x;
    const int g0  = blk * MLP_G;
    const int b   = g0 >> 12;
    const int tid = threadIdx.x;

    if (tid < NBG) idxs[tid] = g_ballIdx[(g0 + (tid >> 5)) * NSAMP + (tid & 31)];
    if (tid >= 256 && tid < 264) scnt[tid - 256] = g_ballCnt[g0 + (tid - 256)];
    if (tid >= 264 && tid < 288) {
        const int q = (tid - 264) / 3, k = (tid - 264) % 3;
        if (q < 8) c3[q * 3 + k] = newxyz[(g0 + q) * 3 + k];
    }
    if (tid >= 288 && tid < 352)       bss[tid - 288] = b1[tid - 288];
    else if (tid >= 352 && tid < 416)  bss[64 + (tid - 352)] = b2[tid - 352];
    else if (tid >= 416 && tid < 512) {
        const int o = tid - 416;
        bss[128 + o] = b3[o];
    }
    if (tid < 32) bss[128 + 96 + tid] = b3[96 + tid];

    for (int e = tid; e < 64 * 67; e += 512) {
        const int oc = e / 67, i = e % 67;
        w1s[i * W1_STRV + oc] = w1[e];
    }
    for (int e = tid; e < 64 * 64; e += 512) {
        const int oc = e >> 6, i = e & 63;
        w2s[i * W2_STRV + oc] = w2[e];
    }
    for (int e = tid; e < 128 * 64; e += 512) {
        const int oc = e >> 6, i = e & 63;
        w3s[i * W3_STRV + oc] = w3[e];
    }
    __syncthreads();

    const float* xb = xyz + (size_t)b * NN * 3;
    for (int e = tid; e < 67 * NBG; e += 512) {
        const int nbg = e & 255;
        const int i   = e >> 8;
        const int q   = nbg >> 5;
        const int pi  = idxs[nbg];
        float v;
        if (i < 3) v = xb[pi * 3 + i] - c3[q * 3 + i];
        else       v = g_featsT[((size_t)b * NN + pi) * CIN + (i - 3)];
        actA[i * NBS + nbg] = v;
    }
    __syncthreads();

    {
        const int otile = tid & 7, ntile = tid >> 3;
        const int oc0 = otile * 8, nb0 = ntile * 4;
        float acc[8][4];
        const float4 bv0 = *(const float4*)(bss + oc0);
        const float4 bv1 = *(const float4*)(bss + oc0 + 4);
        const float bv[8] = {bv0.x, bv0.y, bv0.z, bv0.w, bv1.x, bv1.y, bv1.z, bv1.w};
#pragma unroll
        for (int jj = 0; jj < 8; jj++)
#pragma unroll
            for (int n = 0; n < 4; n++) acc[jj][n] = bv[jj];
        for (int i = 0; i < 67; i++) {
            const float4 wA = *(const float4*)(w1s + i * W1_STRV + oc0);
            const float4 wB = *(const float4*)(w1s + i * W1_STRV + oc0 + 4);
            const float4 xv = *(const float4*)(actA + i * NBS + nb0);
            const float wr[8] = {wA.x, wA.y, wA.z, wA.w, wB.x, wB.y, wB.z, wB.w};
            const float xr[4] = {xv.x, xv.y, xv.z, xv.w};
#pragma unroll
            for (int jj = 0; jj < 8; jj++)
#pragma unroll
                for (int n = 0; n < 4; n++) acc[jj][n] += wr[jj] * xr[n];
        }
#pragma unroll
        for (int jj = 0; jj < 8; jj++) {
            float4 o;
            o.x = fmaxf(acc[jj][0], 0.f); o.y = fmaxf(acc[jj][1], 0.f);
            o.z = fmaxf(acc[jj][2], 0.f); o.w = fmaxf(acc[jj][3], 0.f);
            *(float4*)(actB + (oc0 + jj) * NBS + nb0) = o;
        }
    }
    __syncthreads();

    {
        const int otile = tid & 7, ntile = tid >> 3;
        const int oc0 = otile * 8, nb0 = ntile * 4;
        float acc[8][4];
        const float4 bv0 = *(const float4*)(bss + 64 + oc0);
        const float4 bv1 = *(const float4*)(bss + 64 + oc0 + 4);
        const float bv[8] = {bv0.x, bv0.y, bv0.z, bv0.w, bv1.x, bv1.y, bv1.z, bv1.w};
#pragma unroll
        for (int jj = 0; jj < 8; jj++)
#pragma unroll
            for (int n = 0; n < 4; n++) acc[jj][n] = bv[jj];
        for (int i = 0; i < 64; i++) {
            const float4 wA = *(const float4*)(w2s + i * W2_STRV + oc0);
            const float4 wB = *(const float4*)(w2s + i * W2_STRV + oc0 + 4);
            const float4 xv = *(const float4*)(actB + i * NBS + nb0);
            const float wr[8] = {wA.x, wA.y, wA.z, wA.w, wB.x, wB.y, wB.z, wB.w};
            const float xr[4] = {xv.x, xv.y, xv.z, xv.w};
#pragma unroll
            for (int jj = 0; jj < 8; jj++)
#pragma unroll
                for (int n = 0; n < 4; n++) acc[jj][n] += wr[jj] * xr[n];
        }
        __syncthreads();
#pragma unroll
        for (int jj = 0; jj < 8; jj++) {
            float4 o;
            o.x = fmaxf(acc[jj][0], 0.f); o.y = fmaxf(acc[jj][1], 0.f);
            o.z = fmaxf(acc[jj][2], 0.f); o.w = fmaxf(acc[jj][3], 0.f);
            *(float4*)(actA + (oc0 + jj) * NBS + nb0) = o;
        }
    }
    __syncthreads();

    {
        const int otile = tid & 15, ntile = tid >> 4;
        const int oc0 = otile * 8, nb0 = ntile * 8;
        float acc[8][8];
        const float4 bv0 = *(const float4*)(bss + 128 + oc0);
        const float4 bv1 = *(const float4*)(bss + 128 + oc0 + 4);
        const float bv[8] = {bv0.x, bv0.y, bv0.z, bv0.w, bv1.x, bv1.y, bv1.z, bv1.w};
#pragma unroll
        for (int jj = 0; jj < 8; jj++)
#pragma unroll
            for (int n = 0; n < 8; n++) acc[jj][n] = bv[jj];
        for (int i = 0; i < 64; i++) {
            const float4 wA = *(const float4*)(w3s + i * W3_STRV + oc0);
            const float4 wB = *(const float4*)(w3s + i * W3_STRV + oc0 + 4);
            const float4 x0 = *(const float4*)(actA + i * NBS + nb0);
            const float4 x1 = *(const float4*)(actA + i * NBS + nb0 + 4);
            const float wr[8] = {wA.x, wA.y, wA.z, wA.w, wB.x, wB.y, wB.z, wB.w};
            const float xr[8] = {x0.x, x0.y, x0.z, x0.w, x1.x, x1.y, x1.z, x1.w};
#pragma unroll
            for (int jj = 0; jj < 8; jj++)
#pragma unroll
                for (int n = 0; n < 8; n++) acc[jj][n] += wr[jj] * xr[n];
        }
        const int grp = nb0 >> 5;
        const int ntl = (nb0 & 31) >> 3;
#pragma unroll
        for (int jj = 0; jj < 8; jj++) {
            float m = acc[jj][0];
#pragma unroll
            for (int n = 1; n < 8; n++) m = fmaxf(m, acc[jj][n]);
            m = fmaxf(m, 0.f);
            poolbuf[(oc0 + jj) * 32 + grp * 4 + ntl] = m;
        }
    }
    __syncthreads();

#pragma unroll
    for (int r = 0; r < 2; r++) {
        const int idx = tid + 512 * r;
        const int oc = idx & 127, q = idx >> 7;
        const float4 pv = *(const float4*)(poolbuf + oc * 32 + q * 4);
        const float m = fmaxf(fmaxf(pv.x, pv.y), fmaxf(pv.z, pv.w));
        pooled[q * 128 + oc] = (scnt[q] > 0) ? m : 0.f;
    }
    __syncthreads();

#pragma unroll
    for (int r = 0; r < 2; r++) {
        const int idx = tid + 512 * r;
        const int o = idx & 127, q = idx >> 7;
        float acc = ba[o];
        const float4* w4 = (const float4*)(wa + o * 128);
        const float* pv = pooled + q * 128;
#pragma unroll 8
        for (int i = 0; i < 32; i++) {
            const float4 wv = __ldg(w4 + i);
            acc += pv[4 * i + 0] * wv.x;
            acc += pv[4 * i + 1] * wv.y;
            acc += pv[4 * i + 2] * wv.z;
            acc += pv[4 * i + 3] * wv.w;
        }
        const float a = fmaxf(acc, 0.f);
        aggv[q * 128 + o] = a;
        const int gg = g0 + q;
        d_out[OUT_FEAT_OFF + ((size_t)(b * 128 + o)) * SS + (gg & 4095)] = a;
    }
    __syncthreads();

    {
        const int wq = tid >> 5, lane = tid & 31;
        if (wq < MLP_G) {
            float p = 0.f;
#pragma unroll
            for (int k = 0; k < 4; k++) {
                const int i = k * 32 + lane;
                p += aggv[wq * 128 + i] * wc[i];
            }
#pragma unroll
            for (int off = 16; off; off >>= 1)
                p += __shfl_down_sync(0xffffffffu, p, off);
            if (lane == 0) {
                const int gg = g0 + wq;
                d_out[OUT_SCORE_OFF + b * SS + (gg & 4095)] = p + bc[0];
            }
        }
    }
}

// =================================================================
// launch
// =================================================================
extern "C" void kernel_launch(void* const* d_in, const int* in_sizes, int n_in,
                              void* d_out, int out_size)
{
    const float* xyz      = (const float*)d_in[0];
    const float* features = (const float*)d_in[1];
    const float* w1 = (const float*)d_in[2];
    const float* b1 = (const float*)d_in[3];
    const float* w2 = (const float*)d_in[4];
    const float* b2 = (const float*)d_in[5];
    const float* w3 = (const float*)d_in[6];
    const float* b3 = (const float*)d_in[7];
    const float* wa = (const float*)d_in[8];
    const float* ba = (const float*)d_in[9];
    const float* wc = (const float*)d_in[10];
    const float* bc = (const float*)d_in[11];
    float* out = (float*)d_out;

    static bool attr_set = false;
    if (!attr_set) {
        cudaFuncSetAttribute(fps_kernel, cudaFuncAttributeMaxDynamicSharedMemorySize,
                             FPS_SMEM_BYTES);
        cudaFuncSetAttribute(group_mlp_kernel, cudaFuncAttributeMaxDynamicSharedMemorySize,
                             MLP2_SMEM_FLOATS * (int)sizeof(float));
        attr_set = true;
    }

    // 1) transpose features to (B,N,C)
    transpose_kernel<<<dim3(NN / 32, CIN / 32, BB), dim3(32, 32)>>>(features);

    // 2) FPS -> writes new_xyz into d_out[0:24576)
    fps_kernel<<<BB, FPS_T, FPS_SMEM_BYTES>>>(xyz, out + OUT_XYZ_OFF);

    // 3) ball query
    ballq_kernel<<<(BB * SS) / 8, 256>>>(xyz, out + OUT_XYZ_OFF);

    // 4) fused gather + MLP + pool + agg + score (8 groups/block)
    group_mlp_kernel<<<(BB * SS) / MLP_G, 512, MLP2_SMEM_FLOATS * sizeof(float)>>>(
        xyz, out + OUT_XYZ_OFF,
        w1, b1, w2, b2, w3, b3, wa, ba, wc, bc, out);
}

// round 14
// speedup vs baseline: 1.1323x; 1.1323x over previous
#include <cuda_runtime.h>
#include <cuda_bf16.h>

// Problem constants
#define BB 2
#define NN 16384
#define CIN 64
#define SS 4096
#define NSAMP 32

// Output layout (floats): new_xyz | new_features | scores
#define OUT_XYZ_OFF   0
#define OUT_FEAT_OFF  (BB * SS * 3)                       // 24576
#define OUT_SCORE_OFF (OUT_FEAT_OFF + BB * 128 * SS)      // 1073152

// ---------------- scratch (no allocations allowed) ----------------
__device__ float g_featsT[BB * NN * CIN];    // (B,N,C) transposed features, 8 MB
__device__ int   g_ballIdx[BB * SS * NSAMP]; // neighbor indices
__device__ int   g_ballCnt[BB * SS];         // in-ball counts (0 => empty)

typedef unsigned long long u64;

// =================================================================
// Kernel 1: FPS (one 512-thread block per batch; 16 warps)
//  - cold points in 256 Morton chunks of 64 (tight boxes); warp w
//    owns chunks w+16m (m=0..15); lane m holds that chunk's AABB+key
//    in registers; lane 16 holds the warp's hot chunk.
//  - xy read from smem during scans (no reg spills at 512 thr);
//    z + running dist in registers (2 pts/lane/chunk).
//  - DIRTY-SKIP scans; REDUX argmax (dist, then inv) => exact
//    (dist<<14)|(16383-idx) winner, first-index tie-break.
//  - cwin warp-private; cross-warp s_wm/s_wwin parity-buffered =>
//    ONE barrier per iteration.
// =================================================================
#define FPS_T   512
#define FPS_W   16
#define CPW     16       // cold chunks per warp
#define CSZ     64       // points per cold chunk
#define NCHMAX  256
#define HOTCAP  1024
#define HOT_TGT 768
#define NCELL   2048

// smem: cxy 131072 | inv16 32768 | hot4 16384 | hist 8192 | cwin f4[272]=4352
#define FPS_SMEM_BYTES (131072 + 32768 + 16384 + 8192 + 4352)

__device__ __forceinline__ float r2_rn(float x, float y, float z)
{
    return __fadd_rn(__fadd_rn(__fmul_rn(x, x), __fmul_rn(y, y)), __fmul_rn(z, z));
}
__device__ __forceinline__ float dist_rn(float x, float y, float z,
                                         float nx, float ny, float nz)
{
    const float dx = __fadd_rn(x, nx);
    const float dy = __fadd_rn(y, ny);
    const float dz = __fadd_rn(z, nz);
    return __fadd_rn(__fadd_rn(__fmul_rn(dx, dx), __fmul_rn(dy, dy)), __fmul_rn(dz, dz));
}

__device__ __forceinline__ int fps_cell(float x, float y, float z,
                                        float mnx, float mny, float mnz,
                                        float isx, float isy, float isz)
{
    int qx = __float2int_rd((x - mnx) * isx); qx = max(0, min(15, qx));
    int qy = __float2int_rd((y - mny) * isy); qy = max(0, min(15, qy));
    int qz = __float2int_rd((z - mnz) * isz); qz = max(0, min(7,  qz));
    return  (qx & 1)        | ((qy & 1) << 1)        | ((qz & 1) << 2)
         | (((qx >> 1) & 1) << 3) | (((qy >> 1) & 1) << 4) | (((qz >> 1) & 1) << 5)
         | (((qx >> 2) & 1) << 6) | (((qy >> 2) & 1) << 7) | (((qz >> 2) & 1) << 8)
         | (((qx >> 3) & 1) << 9) | (((qy >> 3) & 1) << 10);
}

__global__ __launch_bounds__(FPS_T) void fps_kernel(
    const float* __restrict__ xyz, float* __restrict__ out_newxyz)
{
    extern __shared__ unsigned char raw[];
    float2*         cxy   = (float2*)raw;                      // [16384]
    unsigned short* inv16 = (unsigned short*)(cxy + NN);       // [16384]
    float4*         hot4  = (float4*)(inv16 + NN);             // [1024]
    unsigned*       hist  = (unsigned*)(hot4 + HOTCAP);        // [2048]
    float4*         cwin  = (float4*)(hist + NCELL);           // [272]: 0-255 cold, 256-271 hot

    __shared__ u64      s_wm[2][FPS_W];
    __shared__ float4   s_wwin[2][FPS_W];
    __shared__ float    s_wred[FPS_W][6];
    __shared__ unsigned s_wsum[FPS_W], s_wbase[FPS_W];
    __shared__ unsigned s_rh[128];
    __shared__ float    s_r2b, s_thresh;
    __shared__ float    s_grid[6];
    __shared__ unsigned s_hotCnt;

    const int b    = blockIdx.x;
    const int tid  = threadIdx.x;
    const int lane = tid & 31, w = tid >> 5;
    const float* xb = xyz + (size_t)b * NN * 3;

    // ---- pass 0: global AABB ----
    {
        float mnx = 1e30f, mny = 1e30f, mnz = 1e30f;
        float mxx = -1e30f, mxy = -1e30f, mxz = -1e30f;
        for (int i = tid; i < NN; i += FPS_T) {
            const float x = xb[3 * i], y = xb[3 * i + 1], z = xb[3 * i + 2];
            mnx = fminf(mnx, x); mny = fminf(mny, y); mnz = fminf(mnz, z);
            mxx = fmaxf(mxx, x); mxy = fmaxf(mxy, y); mxz = fmaxf(mxz, z);
        }
#pragma unroll
        for (int off = 16; off; off >>= 1) {
            mnx = fminf(mnx, __shfl_xor_sync(0xffffffffu, mnx, off));
            mny = fminf(mny, __shfl_xor_sync(0xffffffffu, mny, off));
            mnz = fminf(mnz, __shfl_xor_sync(0xffffffffu, mnz, off));
            mxx = fmaxf(mxx, __shfl_xor_sync(0xffffffffu, mxx, off));
            mxy = fmaxf(mxy, __shfl_xor_sync(0xffffffffu, mxy, off));
            mxz = fmaxf(mxz, __shfl_xor_sync(0xffffffffu, mxz, off));
        }
        if (lane == 0) {
            s_wred[w][0] = mnx; s_wred[w][1] = mny; s_wred[w][2] = mnz;
            s_wred[w][3] = mxx; s_wred[w][4] = mxy; s_wred[w][5] = mxz;
        }
    }
    for (int i = tid; i < NCELL; i += FPS_T) hist[i] = 0;
    if (tid < 128) s_rh[tid] = 0;
    if (tid == 0) s_hotCnt = 0;
    __syncthreads();
    if (tid == 0) {
        float a0 = 1e30f, a1 = 1e30f, a2 = 1e30f, a3 = -1e30f, a4 = -1e30f, a5 = -1e30f;
        for (int i = 0; i < FPS_W; i++) {
            a0 = fminf(a0, s_wred[i][0]); a1 = fminf(a1, s_wred[i][1]); a2 = fminf(a2, s_wred[i][2]);
            a3 = fmaxf(a3, s_wred[i][3]); a4 = fmaxf(a4, s_wred[i][4]); a5 = fmaxf(a5, s_wred[i][5]);
        }
        s_grid[0] = a0; s_grid[1] = a1; s_grid[2] = a2;
        s_grid[3] = 16.f / fmaxf(a3 - a0, 1e-9f);
        s_grid[4] = 16.f / fmaxf(a4 - a1, 1e-9f);
        s_grid[5] = 8.f  / fmaxf(a5 - a2, 1e-9f);
        const float bx = fmaxf(fabsf(a0), fabsf(a3));
        const float by = fmaxf(fabsf(a1), fabsf(a4));
        const float bz = fmaxf(fabsf(a2), fabsf(a5));
        s_r2b = bx * bx + by * by + bz * bz + 1e-6f;
    }
    __syncthreads();

    const float gmnx = s_grid[0], gmny = s_grid[1], gmnz = s_grid[2];
    const float isx = s_grid[3], isy = s_grid[4], isz = s_grid[5];
    const float r2b = s_r2b;

    // ---- pass 1: r2 histogram -> deterministic hot threshold ----
    for (int i = tid; i < NN; i += FPS_T) {
        const float r2 = r2_rn(xb[3 * i], xb[3 * i + 1], xb[3 * i + 2]);
        const int bin = min(127, (int)(r2 * (128.f / r2b)));
        atomicAdd(&s_rh[bin], 1u);
    }
    __syncthreads();
    if (tid == 0) {
        unsigned acc = 0;
        float thr = 3e38f;
        for (int q = 127; q >= 0; q--) {
            if (acc + s_rh[q] > HOT_TGT) break;
            acc += s_rh[q];
            thr = (float)q * (r2b / 128.f);
        }
        s_thresh = thr;
    }
    __syncthreads();
    const float thresh = s_thresh;

    // ---- pass 2: Morton histogram over cold ----
    for (int i = tid; i < NN; i += FPS_T) {
        const float x = xb[3 * i], y = xb[3 * i + 1], z = xb[3 * i + 2];
        if (r2_rn(x, y, z) < thresh) {
            const int c = fps_cell(x, y, z, gmnx, gmny, gmnz, isx, isy, isz);
            atomicAdd(&hist[c], 1u);
        }
    }
    __syncthreads();

    // ---- exclusive scan of hist[2048] ----
    {
        const int t4 = tid * 4;
        unsigned v[4], s = 0;
#pragma unroll
        for (int q = 0; q < 4; q++) { v[q] = hist[t4 + q]; s += v[q]; }
        unsigned inc = s;
#pragma unroll
        for (int off = 1; off < 32; off <<= 1) {
            const unsigned n = __shfl_up_sync(0xffffffffu, inc, off);
            if (lane >= off) inc += n;
        }
        if (lane == 31) s_wsum[w] = inc;
        __syncthreads();
        if (tid < FPS_W) {
            const unsigned ws = s_wsum[tid];
            unsigned winc = ws;
#pragma unroll
            for (int off = 1; off < FPS_W; off <<= 1) {
                const unsigned n = __shfl_up_sync(0x0000ffffu, winc, off);
                if ((int)tid >= off) winc += n;
            }
            s_wbase[tid] = winc - ws;
        }
        __syncthreads();
        unsigned run = s_wbase[w] + (inc - s);
#pragma unroll
        for (int q = 0; q < 4; q++) { hist[t4 + q] = run; run += v[q]; }
    }
    __syncthreads();

    // ---- pass 3: scatter hot / cold (inv = 16383 - i) ----
    for (int i = tid; i < NN; i += FPS_T) {
        const float x = xb[3 * i], y = xb[3 * i + 1], z = xb[3 * i + 2];
        if (r2_rn(x, y, z) >= thresh) {
            const unsigned pos = atomicAdd(&s_hotCnt, 1u);
            hot4[pos] = make_float4(x, y, z, __uint_as_float(16383u - (unsigned)i));
        } else {
            const int c = fps_cell(x, y, z, gmnx, gmny, gmnz, isx, isy, isz);
            const unsigned slot = atomicAdd(&hist[c], 1u);
            cxy[slot]   = make_float2(x, y);
            inv16[slot] = (unsigned short)(16383u - (unsigned)i);
        }
    }
    __syncthreads();

    const int hc    = (int)s_hotCnt;
    const int coldN = NN - hc;
    const int nch   = (coldN + CSZ - 1) >> 6;   // 64-pt chunks

    // pads (duplicates: identical keys/coords, harmless)
    for (int s2 = hc + tid; s2 < HOTCAP; s2 += FPS_T)
        hot4[s2] = (hc > 0) ? hot4[0]
                            : make_float4(xb[0], xb[1], xb[2], __uint_as_float(16383u));
    for (int s2 = coldN + tid; s2 < nch * CSZ; s2 += FPS_T) {
        cxy[s2]   = cxy[coldN - 1];
        inv16[s2] = inv16[coldN - 1];
    }
    __syncthreads();

    // ---- per-lane chunk metadata (registers) ----
    // lanes 0..15: cold chunk (w + 16*lane); lane 16: hot chunk
    float bx0 = 1e30f, bx1 = 1e30f, bx2 = 1e30f;
    float bx3 = -1e30f, bx4 = -1e30f, bx5 = -1e30f;
    u64   mykey = 0ull;

    // hot -> registers (2 pts/thread) + hot AABB -> lane 16
    float hx[2], hy[2], hz[2], hd[2];
    unsigned hinv[2];
    {
        float hmn0 = 1e30f, hmn1 = 1e30f, hmn2 = 1e30f;
        float hmx0 = -1e30f, hmx1 = -1e30f, hmx2 = -1e30f;
#pragma unroll
        for (int k = 0; k < 2; k++) {
            const float4 h = hot4[tid + FPS_T * k];
            hx[k] = h.x; hy[k] = h.y; hz[k] = h.z;
            hinv[k] = __float_as_uint(h.w);
            hd[k] = 1e10f;
            hmn0 = fminf(hmn0, h.x); hmn1 = fminf(hmn1, h.y); hmn2 = fminf(hmn2, h.z);
            hmx0 = fmaxf(hmx0, h.x); hmx1 = fmaxf(hmx1, h.y); hmx2 = fmaxf(hmx2, h.z);
        }
#pragma unroll
        for (int off = 16; off; off >>= 1) {
            hmn0 = fminf(hmn0, __shfl_xor_sync(0xffffffffu, hmn0, off));
            hmn1 = fminf(hmn1, __shfl_xor_sync(0xffffffffu, hmn1, off));
            hmn2 = fminf(hmn2, __shfl_xor_sync(0xffffffffu, hmn2, off));
            hmx0 = fmaxf(hmx0, __shfl_xor_sync(0xffffffffu, hmx0, off));
            hmx1 = fmaxf(hmx1, __shfl_xor_sync(0xffffffffu, hmx1, off));
            hmx2 = fmaxf(hmx2, __shfl_xor_sync(0xffffffffu, hmx2, off));
        }
        if (lane == 16) {
            bx0 = hmn0; bx1 = hmn1; bx2 = hmn2;
            bx3 = hmx0; bx4 = hmx1; bx5 = hmx2;
            mykey = ((u64)__float_as_uint(1e10f)) << 14;
        }
    }

    // cold z + dist regs (16 chunks x 2 pts/lane); AABB -> lane m
    float cz[32], cd[32];
#pragma unroll
    for (int k = 0; k < 32; k++) { cz[k] = 0.f; cd[k] = 1e10f; }

#pragma unroll
    for (int m = 0; m < CPW; m++) {
        const int c = w + FPS_W * m;
        if (c < nch) {
            float lmn0 = 1e30f, lmn1 = 1e30f, lmn2 = 1e30f;
            float lmx0 = -1e30f, lmx1 = -1e30f, lmx2 = -1e30f;
#pragma unroll
            for (int k = 0; k < 2; k++) {
                const int slot = c * CSZ + lane + 32 * k;
                const float2 xy = cxy[slot];
                const int oi = 16383 - (int)inv16[slot];
                const float z = __ldg(xb + 3 * oi + 2);
                cz[m * 2 + k] = z;
                lmn0 = fminf(lmn0, xy.x); lmn1 = fminf(lmn1, xy.y); lmn2 = fminf(lmn2, z);
                lmx0 = fmaxf(lmx0, xy.x); lmx1 = fmaxf(lmx1, xy.y); lmx2 = fmaxf(lmx2, z);
            }
#pragma unroll
            for (int off = 16; off; off >>= 1) {
                lmn0 = fminf(lmn0, __shfl_xor_sync(0xffffffffu, lmn0, off));
                lmn1 = fminf(lmn1, __shfl_xor_sync(0xffffffffu, lmn1, off));
                lmn2 = fminf(lmn2, __shfl_xor_sync(0xffffffffu, lmn2, off));
                lmx0 = fmaxf(lmx0, __shfl_xor_sync(0xffffffffu, lmx0, off));
                lmx1 = fmaxf(lmx1, __shfl_xor_sync(0xffffffffu, lmx1, off));
                lmx2 = fmaxf(lmx2, __shfl_xor_sync(0xffffffffu, lmx2, off));
            }
            if (lane == m) {
                bx0 = lmn0; bx1 = lmn1; bx2 = lmn2;
                bx3 = lmx0; bx4 = lmx1; bx5 = lmx2;
                mykey = ((u64)__float_as_uint(1e10f)) << 14;
            }
        }
    }
    __syncthreads();

    float* outx = out_newxyz + (size_t)b * SS * 3;
    float ccx = __ldg(xb + 0), ccy = __ldg(xb + 1), ccz = __ldg(xb + 2);

    // per-warp cached summary (registers, refreshed on wflag)
    u64    wmreg = 0ull;
    float4 wwinreg = make_float4(0.f, 0.f, 0.f, 0.f);

    // ---- main loop: ONE barrier per iteration (parity buffers) ----
    for (int j = 0; j < SS; j++) {
        const int p = j & 1;
        if (tid == 0) {
            outx[3 * j + 0] = ccx;
            outx[3 * j + 1] = ccy;
            outx[3 * j + 2] = ccz;
        }
        const float nx = -ccx, ny = -ccy, nz = -ccz;

        // --- prune: pure register math, lanes 0..16 ---
        bool act = false;
        if (lane < 17) {
            const float dxm = fmaxf(fmaxf(__fadd_rn(bx0, nx), -__fadd_rn(bx3, nx)), 0.f);
            const float dym = fmaxf(fmaxf(__fadd_rn(bx1, ny), -__fadd_rn(bx4, ny)), 0.f);
            const float dzm = fmaxf(fmaxf(__fadd_rn(bx2, nz), -__fadd_rn(bx5, nz)), 0.f);
            const float dmin2 = __fadd_rn(__fadd_rn(__fmul_rn(dxm, dxm), __fmul_rn(dym, dym)),
                                          __fmul_rn(dzm, dzm));
            const float cm = __uint_as_float((unsigned)(mykey >> 14));
            act = dmin2 < cm;   // mykey==0 for invalid chunks => never active
        }
        const unsigned mask = __ballot_sync(0xffffffffu, act);
        bool wflag = false;

        // --- hot scan (bit 16) ---
        if ((mask >> 16) & 1u) {
            u64 bk = 0ull; float hbx = 0.f, hby = 0.f, hbz = 0.f;
            bool chg = false;
#pragma unroll
            for (int k = 0; k < 2; k++) {
                const float d = dist_rn(hx[k], hy[k], hz[k], nx, ny, nz);
                const float old = hd[k];
                const float nd = fminf(old, d);
                chg |= (nd < old);
                hd[k] = nd;
                const u64 key = ((u64)__float_as_uint(nd) << 14) | (u64)hinv[k];
                if (key > bk) { bk = key; hbx = hx[k]; hby = hy[k]; hbz = hz[k]; }
            }
            if (__ballot_sync(0xffffffffu, chg)) {
                const unsigned d32 = (unsigned)(bk >> 14);
                const unsigned K32 = __reduce_max_sync(0xffffffffu, d32);
                const unsigned myinv = (unsigned)(bk & 0x3FFFull);
                const unsigned I = __reduce_max_sync(0xffffffffu, (d32 == K32) ? myinv : 0u);
                const unsigned own = __ballot_sync(0xffffffffu, (d32 == K32) && (myinv == I));
                if (lane == (int)(__ffs(own) - 1)) cwin[256 + w] = make_float4(hbx, hby, hbz, 0.f);
                if (lane == 16) mykey = ((u64)K32 << 14) | (u64)I;
                wflag = true;
            }
        }

        // --- cold scans (64-pt chunks): dists; keys only if dirty ---
#pragma unroll
        for (int m = 0; m < CPW; m++) {
            if ((mask >> m) & 1u) {   // warp-uniform
                const int c = w + FPS_W * m;
                float lx[2], ly[2];
                bool chg = false;
#pragma unroll
                for (int k = 0; k < 2; k++) {
                    const int slot = c * CSZ + lane + 32 * k;
                    const float2 xy = cxy[slot];
                    lx[k] = xy.x; ly[k] = xy.y;
                    const float d = dist_rn(xy.x, xy.y, cz[m * 2 + k], nx, ny, nz);
                    const float old = cd[m * 2 + k];
                    const float nd = fminf(old, d);
                    chg |= (nd < old);
                    cd[m * 2 + k] = nd;
                }
                if (__ballot_sync(0xffffffffu, chg)) {
                    u64 bk = 0ull; float cbx = 0.f, cby = 0.f, cbz = 0.f;
#pragma unroll
                    for (int k = 0; k < 2; k++) {
                        const int slot = c * CSZ + lane + 32 * k;
                        const u64 key = ((u64)__float_as_uint(cd[m * 2 + k]) << 14)
                                      | (u64)inv16[slot];
                        if (key > bk) {
                            bk = key;
                            cbx = lx[k]; cby = ly[k]; cbz = cz[m * 2 + k];
                        }
                    }
                    const unsigned d32 = (unsigned)(bk >> 14);
                    const unsigned K32 = __reduce_max_sync(0xffffffffu, d32);
                    const unsigned myinv = (unsigned)(bk & 0x3FFFull);
                    const unsigned I = __reduce_max_sync(0xffffffffu, (d32 == K32) ? myinv : 0u);
                    const unsigned own = __ballot_sync(0xffffffffu, (d32 == K32) && (myinv == I));
                    if (lane == (int)(__ffs(own) - 1)) cwin[c] = make_float4(cbx, cby, cbz, 0.f);
                    if (lane == m) mykey = ((u64)K32 << 14) | (u64)I;
                    wflag = true;
                }
            }
        }

        // --- warp summary refresh (only if any owned chunk changed) ---
        if (wflag) {
            const unsigned d32 = (lane < 17) ? (unsigned)(mykey >> 14) : 0u;
            const unsigned K = __reduce_max_sync(0xffffffffu, d32);
            const unsigned I = __reduce_max_sync(0xffffffffu,
                (d32 == K) ? (unsigned)(mykey & 0x3FFFull) : 0u);
            wmreg = ((u64)K << 14) | (u64)I;
            const unsigned own = __ballot_sync(0xffffffffu,
                (lane < 17) && (mykey == wmreg));
            const int sl = (int)(__ffs(own) - 1);
            const int src = (sl < 16) ? (w + FPS_W * sl) : (256 + w);
            wwinreg = cwin[src];   // warp-private read (broadcast LDS)
        }
        if (lane == 0) {
            s_wm[p][w] = wmreg;
            s_wwin[p][w] = wwinreg;
        }
        __syncthreads();   // the ONLY barrier in the loop

        // --- block argmax over 16 warp keys (every warp, redundant) ---
        {
            const u64 k = (lane < FPS_W) ? s_wm[p][lane] : 0ull;
            const unsigned d32 = (unsigned)(k >> 14);
            const unsigned K = __reduce_max_sync(0xffffffffu, d32);
            const unsigned I = __reduce_max_sync(0xffffffffu,
                (d32 == K) ? (unsigned)(k & 0x3FFFull) : 0u);
            const u64 W = ((u64)K << 14) | (u64)I;
            const unsigned has = __ballot_sync(0xffffffffu, (lane < FPS_W) && (k == W));
            const int wi = (int)(__ffs(has) - 1);
            const float4 wv = s_wwin[p][wi];
            ccx = wv.x; ccy = wv.y; ccz = wv.z;
        }
        // no second barrier: next iteration writes parity buffer p^1
    }
}

// =================================================================
// Kernel 2: transpose features (B,C,N) -> (B,N,C)
// =================================================================
__global__ void transpose_kernel(const float* __restrict__ f)
{
    __shared__ float tile[32][33];
    const int b  = blockIdx.z;
    const int n0 = blockIdx.x * 32;
    const int c0 = blockIdx.y * 32;
    const int tx = threadIdx.x, ty = threadIdx.y;
    tile[ty][tx] = f[((size_t)b * CIN + (c0 + ty)) * NN + n0 + tx];
    __syncthreads();
    g_featsT[((size_t)b * NN + (n0 + ty)) * CIN + c0 + tx] = tile[tx][ty];
}

// =================================================================
// Kernel 3: ball query (one warp per group), first-32-ascending
// =================================================================
__global__ void ballq_kernel(const float* __restrict__ xyz,
                             const float* __restrict__ newxyz)
{
    const int g    = blockIdx.x * 8 + (threadIdx.x >> 5);
    const int lane = threadIdx.x & 31;
    const int b    = g >> 12;
    const float* xb = xyz + (size_t)b * NN * 3;

    const float cx = newxyz[g * 3 + 0];
    const float cy = newxyz[g * 3 + 1];
    const float cz = newxyz[g * 3 + 2];

    int* out = g_ballIdx + g * NSAMP;
    int cnt = 0;

    for (int base = 0; base < NN && cnt < NSAMP; base += 32) {
        const int i = base + lane;
        const float dx = xb[3 * i + 0] - cx;
        const float dy = xb[3 * i + 1] - cy;
        const float dz = xb[3 * i + 2] - cz;
        const float d2 = __fadd_rn(__fadd_rn(__fmul_rn(dx, dx), __fmul_rn(dy, dy)),
                                   __fmul_rn(dz, dz));
        const bool inb = d2 < 0.25f;
        const unsigned m = __ballot_sync(0xffffffffu, inb);
        const int pos = cnt + __popc(m & ((1u << lane) - 1u));
        if (inb && pos < NSAMP) out[pos] = i;
        cnt += __popc(m);
    }
    __syncwarp();
    if (cnt == 0) {
        out[lane] = 0;
    } else if (cnt < NSAMP) {
        const int first = out[0];
        if (lane >= cnt) out[lane] = first;
    }
    if (lane == 0) g_ballCnt[g] = cnt;
}

// =================================================================
// Kernel 4: fused gather + MLP + pool + agg + score, 8 GROUPS/BLOCK,
// 512 threads. Pool/agg buffers alias dead h1 (actB) storage.
// =================================================================
#define MLP_G     8
#define W1_STRV   72
#define W2_STRV   72
#define W3_STRV   136
#define NBG       256
#define NBS       264
#define W1F       (67 * W1_STRV)
#define W2F       (64 * W2_STRV)
#define W3F       (64 * W3_STRV)
#define ACTA_F    (67 * NBS)
#define ACTB_F    (64 * NBS)
#define MLP2_SMEM_FLOATS (W1F + W2F + W3F + ACTA_F + ACTB_F)

__global__ __launch_bounds__(512, 1) void group_mlp_kernel(
    const float* __restrict__ xyz,
    const float* __restrict__ newxyz,
    const float* __restrict__ w1, const float* __restrict__ b1,
    const float* __restrict__ w2, const float* __restrict__ b2,
    const float* __restrict__ w3, const float* __restrict__ b3,
    const float* __restrict__ wa, const float* __restrict__ ba,
    const float* __restrict__ wc, const float* __restrict__ bc,
    float* __restrict__ d_out)
{
    extern __shared__ float sm[];
    float* w1s     = sm;
    float* w2s     = w1s + W1F;
    float* w3s     = w2s + W2F;
    float* actA    = w3s + W3F;
    float* actB    = actA + ACTA_F;
    float* poolbuf = actB;
    float* pooled  = actB + 4096;
    float* aggv    = actB + 5120;

    __shared__ float bss[384];
    __shared__ float c3[32];
    __shared__ int   idxs[NBG];
    __shared__ int   scnt[8];

    const int blk = blockIdx.x;
    const int g0  = blk * MLP_G;
    const int b   = g0 >> 12;
    const int tid = threadIdx.x;

    if (tid < NBG) idxs[tid] = g_ballIdx[(g0 + (tid >> 5)) * NSAMP + (tid & 31)];
    if (tid >= 256 && tid < 264) scnt[tid - 256] = g_ballCnt[g0 + (tid - 256)];
    if (tid >= 264 && tid < 288) {
        const int q = (tid - 264) / 3, k = (tid - 264) % 3;
        if (q < 8) c3[q * 3 + k] = newxyz[(g0 + q) * 3 + k];
    }
    if (tid >= 288 && tid < 352)       bss[tid - 288] = b1[tid - 288];
    else if (tid >= 352 && tid < 416)  bss[64 + (tid - 352)] = b2[tid - 352];
    else if (tid >= 416 && tid < 512) {
        const int o = tid - 416;
        bss[128 + o] = b3[o];
    }
    if (tid < 32) bss[128 + 96 + tid] = b3[96 + tid];

    for (int e = tid; e < 64 * 67; e += 512) {
        const int oc = e / 67, i = e % 67;
        w1s[i * W1_STRV + oc] = w1[e];
    }
    for (int e = tid; e < 64 * 64; e += 512) {
        const int oc = e >> 6, i = e & 63;
        w2s[i * W2_STRV + oc] = w2[e];
    }
    for (int e = tid; e < 128 * 64; e += 512) {
        const int oc = e >> 6, i = e & 63;
        w3s[i * W3_STRV + oc] = w3[e];
    }
    __syncthreads();

    const float* xb = xyz + (size_t)b * NN * 3;
    for (int e = tid; e < 67 * NBG; e += 512) {
        const int nbg = e & 255;
        const int i   = e >> 8;
        const int q   = nbg >> 5;
        const int pi  = idxs[nbg];
        float v;
        if (i < 3) v = xb[pi * 3 + i] - c3[q * 3 + i];
        else       v = g_featsT[((size_t)b * NN + pi) * CIN + (i - 3)];
        actA[i * NBS + nbg] = v;
    }
    __syncthreads();

    {
        const int otile = tid & 7, ntile = tid >> 3;
        const int oc0 = otile * 8, nb0 = ntile * 4;
        float acc[8][4];
        const float4 bv0 = *(const float4*)(bss + oc0);
        const float4 bv1 = *(const float4*)(bss + oc0 + 4);
        const float bv[8] = {bv0.x, bv0.y, bv0.z, bv0.w, bv1.x, bv1.y, bv1.z, bv1.w};
#pragma unroll
        for (int jj = 0; jj < 8; jj++)
#pragma unroll
            for (int n = 0; n < 4; n++) acc[jj][n] = bv[jj];
        for (int i = 0; i < 67; i++) {
            const float4 wA = *(const float4*)(w1s + i * W1_STRV + oc0);
            const float4 wB = *(const float4*)(w1s + i * W1_STRV + oc0 + 4);
            const float4 xv = *(const float4*)(actA + i * NBS + nb0);
            const float wr[8] = {wA.x, wA.y, wA.z, wA.w, wB.x, wB.y, wB.z, wB.w};
            const float xr[4] = {xv.x, xv.y, xv.z, xv.w};
#pragma unroll
            for (int jj = 0; jj < 8; jj++)
#pragma unroll
                for (int n = 0; n < 4; n++) acc[jj][n] += wr[jj] * xr[n];
        }
#pragma unroll
        for (int jj = 0; jj < 8; jj++) {
            float4 o;
            o.x = fmaxf(acc[jj][0], 0.f); o.y = fmaxf(acc[jj][1], 0.f);
            o.z = fmaxf(acc[jj][2], 0.f); o.w = fmaxf(acc[jj][3], 0.f);
            *(float4*)(actB + (oc0 + jj) * NBS + nb0) = o;
        }
    }
    __syncthreads();

    {
        const int otile = tid & 7, ntile = tid >> 3;
        const int oc0 = otile * 8, nb0 = ntile * 4;
        float acc[8][4];
        const float4 bv0 = *(const float4*)(bss + 64 + oc0);
        const float4 bv1 = *(const float4*)(bss + 64 + oc0 + 4);
        const float bv[8] = {bv0.x, bv0.y, bv0.z, bv0.w, bv1.x, bv1.y, bv1.z, bv1.w};
#pragma unroll
        for (int jj = 0; jj < 8; jj++)
#pragma unroll
            for (int n = 0; n < 4; n++) acc[jj][n] = bv[jj];
        for (int i = 0; i < 64; i++) {
            const float4 wA = *(const float4*)(w2s + i * W2_STRV + oc0);
            const float4 wB = *(const float4*)(w2s + i * W2_STRV + oc0 + 4);
            const float4 xv = *(const float4*)(actB + i * NBS + nb0);
            const float wr[8] = {wA.x, wA.y, wA.z, wA.w, wB.x, wB.y, wB.z, wB.w};
            const float xr[4] = {xv.x, xv.y, xv.z, xv.w};
#pragma unroll
            for (int jj = 0; jj < 8; jj++)
#pragma unroll
                for (int n = 0; n < 4; n++) acc[jj][n] += wr[jj] * xr[n];
        }
        __syncthreads();
#pragma unroll
        for (int jj = 0; jj < 8; jj++) {
            float4 o;
            o.x = fmaxf(acc[jj][0], 0.f); o.y = fmaxf(acc[jj][1], 0.f);
            o.z = fmaxf(acc[jj][2], 0.f); o.w = fmaxf(acc[jj][3], 0.f);
            *(float4*)(actA + (oc0 + jj) * NBS + nb0) = o;
        }
    }
    __syncthreads();

    {
        const int otile = tid & 15, ntile = tid >> 4;
        const int oc0 = otile * 8, nb0 = ntile * 8;
        float acc[8][8];
        const float4 bv0 = *(const float4*)(bss + 128 + oc0);
        const float4 bv1 = *(const float4*)(bss + 128 + oc0 + 4);
        const float bv[8] = {bv0.x, bv0.y, bv0.z, bv0.w, bv1.x, bv1.y, bv1.z, bv1.w};
#pragma unroll
        for (int jj = 0; jj < 8; jj++)
#pragma unroll
            for (int n = 0; n < 8; n++) acc[jj][n] = bv[jj];
        for (int i = 0; i < 64; i++) {
            const float4 wA = *(const float4*)(w3s + i * W3_STRV + oc0);
            const float4 wB = *(const float4*)(w3s + i * W3_STRV + oc0 + 4);
            const float4 x0 = *(const float4*)(actA + i * NBS + nb0);
            const float4 x1 = *(const float4*)(actA + i * NBS + nb0 + 4);
            const float wr[8] = {wA.x, wA.y, wA.z, wA.w, wB.x, wB.y, wB.z, wB.w};
            const float xr[8] = {x0.x, x0.y, x0.z, x0.w, x1.x, x1.y, x1.z, x1.w};
#pragma unroll
            for (int jj = 0; jj < 8; jj++)
#pragma unroll
                for (int n = 0; n < 8; n++) acc[jj][n] += wr[jj] * xr[n];
        }
        const int grp = nb0 >> 5;
        const int ntl = (nb0 & 31) >> 3;
#pragma unroll
        for (int jj = 0; jj < 8; jj++) {
            float m = acc[jj][0];
#pragma unroll
            for (int n = 1; n < 8; n++) m = fmaxf(m, acc[jj][n]);
            m = fmaxf(m, 0.f);
            poolbuf[(oc0 + jj) * 32 + grp * 4 + ntl] = m;
        }
    }
    __syncthreads();

#pragma unroll
    for (int r = 0; r < 2; r++) {
        const int idx = tid + 512 * r;
        const int oc = idx & 127, q = idx >> 7;
        const float4 pv = *(const float4*)(poolbuf + oc * 32 + q * 4);
        const float m = fmaxf(fmaxf(pv.x, pv.y), fmaxf(pv.z, pv.w));
        pooled[q * 128 + oc] = (scnt[q] > 0) ? m : 0.f;
    }
    __syncthreads();

#pragma unroll
    for (int r = 0; r < 2; r++) {
        const int idx = tid + 512 * r;
        const int o = idx & 127, q = idx >> 7;
        float acc = ba[o];
        const float4* w4 = (const float4*)(wa + o * 128);
        const float* pv = pooled + q * 128;
#pragma unroll 8
        for (int i = 0; i < 32; i++) {
            const float4 wv = __ldg(w4 + i);
            acc += pv[4 * i + 0] * wv.x;
            acc += pv[4 * i + 1] * wv.y;
            acc += pv[4 * i + 2] * wv.z;
            acc += pv[4 * i + 3] * wv.w;
        }
        const float a = fmaxf(acc, 0.f);
        aggv[q * 128 + o] = a;
        const int gg = g0 + q;
        d_out[OUT_FEAT_OFF + ((size_t)(b * 128 + o)) * SS + (gg & 4095)] = a;
    }
    __syncthreads();

    {
        const int wq = tid >> 5, lane = tid & 31;
        if (wq < MLP_G) {
            float p = 0.f;
#pragma unroll
            for (int k = 0; k < 4; k++) {
                const int i = k * 32 + lane;
                p += aggv[wq * 128 + i] * wc[i];
            }
#pragma unroll
            for (int off = 16; off; off >>= 1)
                p += __shfl_down_sync(0xffffffffu, p, off);
            if (lane == 0) {
                const int gg = g0 + wq;
                d_out[OUT_SCORE_OFF + b * SS + (gg & 4095)] = p + bc[0];
            }
        }
    }
}

// =================================================================
// launch
// =================================================================
extern "C" void kernel_launch(void* const* d_in, const int* in_sizes, int n_in,
                              void* d_out, int out_size)
{
    const float* xyz      = (const float*)d_in[0];
    const float* features = (const float*)d_in[1];
    const float* w1 = (const float*)d_in[2];
    const float* b1 = (const float*)d_in[3];
    const float* w2 = (const float*)d_in[4];
    const float* b2 = (const float*)d_in[5];
    const float* w3 = (const float*)d_in[6];
    const float* b3 = (const float*)d_in[7];
    const float* wa = (const float*)d_in[8];
    const float* ba = (const float*)d_in[9];
    const float* wc = (const float*)d_in[10];
    const float* bc = (const float*)d_in[11];
    float* out = (float*)d_out;

    static bool attr_set = false;
    if (!attr_set) {
        cudaFuncSetAttribute(fps_kernel, cudaFuncAttributeMaxDynamicSharedMemorySize,
                             FPS_SMEM_BYTES);
        cudaFuncSetAttribute(group_mlp_kernel, cudaFuncAttributeMaxDynamicSharedMemorySize,
                             MLP2_SMEM_FLOATS * (int)sizeof(float));
        attr_set = true;
    }

    // 1) transpose features to (B,N,C)
    transpose_kernel<<<dim3(NN / 32, CIN / 32, BB), dim3(32, 32)>>>(features);

    // 2) FPS -> writes new_xyz into d_out[0:24576)
    fps_kernel<<<BB, FPS_T, FPS_SMEM_BYTES>>>(xyz, out + OUT_XYZ_OFF);

    // 3) ball query
    ballq_kernel<<<(BB * SS) / 8, 256>>>(xyz, out + OUT_XYZ_OFF);

    // 4) fused gather + MLP + pool + agg + score (8 groups/block)
    group_mlp_kernel<<<(BB * SS) / MLP_G, 512, MLP2_SMEM_FLOATS * sizeof(float)>>>(
        xyz, out + OUT_XYZ_OFF,
        w1, b1, w2, b2, w3, b3, wa, ba, wc, bc, out);
}